// round 3
// baseline (speedup 1.0000x reference)
#include <cuda_runtime.h>
#include <math.h>

// Problem constants (fixed by the reference):
//   x_test: [T, B, F] f32   (d_in[0])
//   w1:     [B, F, H] f32   (d_in[1])
//   b1:     [B, H]    f32   (d_in[2])
//   w2:     [B, H, O] f32   (d_in[3])   O = 1
//   b2:     [B, O]    f32   (d_in[4])
//   out:    [T, B, O] f32
#define T_DIM 4096
#define B_DIM 8
#define F_DIM 512
#define H_DIM 1024

// GEMM tiling: 128x128 block tile, BK=8, 256 threads, 8x8 microtile,
// double-buffered shared memory (one barrier per k-tile).
#define BM 128
#define BN 128
#define BK 8
#define NTILES (F_DIM / BK)   // 64
#define NTHREADS 256
#define AS_STRIDE 132   // padded row stride for As (floats); 132*4B stays 16B-aligned
#define BS_STRIDE 128

// out[t*B + b] = b2[b]  (bias pre-fill; main kernel atomically accumulates)
__global__ void init_out_kernel(const float* __restrict__ b2, float* __restrict__ out) {
    int i = blockIdx.x * blockDim.x + threadIdx.x;
    if (i < T_DIM * B_DIM) {
        out[i] = b2[i % B_DIM];
    }
}

// Fused: h = relu(x @ w1 + b1); out += (h * w2).sum(h)
// Grid: (T/BM, H/BN, B) = (32, 8, 8). Block: 256 threads = 16x16 grid, 8x8 microtile.
__global__ __launch_bounds__(NTHREADS, 2)
void fused_mlp_kernel(const float* __restrict__ x,
                      const float* __restrict__ w1,
                      const float* __restrict__ b1,
                      const float* __restrict__ w2,
                      float* __restrict__ out) {
    __shared__ float As[2][BK][AS_STRIDE];  // x tile, transposed: As[p][k][m]
    __shared__ float Bs[2][BK][BS_STRIDE];  // w1 tile: Bs[p][k][n]

    const int b  = blockIdx.z;
    const int t0 = blockIdx.x * BM;
    const int h0 = blockIdx.y * BN;
    const int tid = threadIdx.x;
    const int tx = tid & 15;   // n-direction: 16 threads x 8 cols = 128
    const int ty = tid >> 4;   // m-direction: 16 threads x 8 rows = 128

    // --- global load mappings (one float4 per thread per tile) ---
    // A: 128 rows x 8 k = 1024 floats = 256 float4.
    const int ra = tid >> 1;          // 0..127 (t-row within tile)
    const int ca = (tid & 1) * 4;     // 0 or 4 (k-col within tile)
    // B: 8 k-rows x 128 cols = 1024 floats = 256 float4.
    const int kb = tid >> 5;          // 0..7   (k-row within tile)
    const int cb = (tid & 31) * 4;    // 0..124 (h-col within tile)

    const float* xp  = x  + ((size_t)(t0 + ra) * B_DIM + b) * F_DIM + ca;
    const float* w1p = w1 + ((size_t)b * F_DIM + kb) * H_DIM + (h0 + cb);

    float acc[8][8];
#pragma unroll
    for (int i = 0; i < 8; i++)
#pragma unroll
        for (int j = 0; j < 8; j++) acc[i][j] = 0.0f;

    // --- prologue: stage tile 0 into buffer 0 ---
    {
        float4 a4 = *reinterpret_cast<const float4*>(xp);
        a4.x = isnan(a4.x) ? 0.0f : a4.x;
        a4.y = isnan(a4.y) ? 0.0f : a4.y;
        a4.z = isnan(a4.z) ? 0.0f : a4.z;
        a4.w = isnan(a4.w) ? 0.0f : a4.w;
        As[0][ca + 0][ra] = a4.x;
        As[0][ca + 1][ra] = a4.y;
        As[0][ca + 2][ra] = a4.z;
        As[0][ca + 3][ra] = a4.w;
        *reinterpret_cast<float4*>(&Bs[0][kb][cb]) =
            *reinterpret_cast<const float4*>(w1p);
    }
    __syncthreads();

    // --- main loop: LDG(next) -> compute(cur) -> STS(next) -> bar ---
    for (int it = 0; it < NTILES; it++) {
        const int p = it & 1;

        float4 nA, nB;
        const bool have_next = (it + 1 < NTILES);
        if (have_next) {
            const int knext = (it + 1) * BK;
            nA = *reinterpret_cast<const float4*>(xp + knext);
            nB = *reinterpret_cast<const float4*>(w1p + (size_t)knext * H_DIM);
        }

#pragma unroll
        for (int k = 0; k < BK; k++) {
            float4 a0 = *reinterpret_cast<const float4*>(&As[p][k][ty * 8]);
            float4 a1 = *reinterpret_cast<const float4*>(&As[p][k][ty * 8 + 4]);
            float4 b0 = *reinterpret_cast<const float4*>(&Bs[p][k][tx * 8]);
            float4 b1v4 = *reinterpret_cast<const float4*>(&Bs[p][k][tx * 8 + 4]);
            float av[8] = {a0.x, a0.y, a0.z, a0.w, a1.x, a1.y, a1.z, a1.w};
            float bv[8] = {b0.x, b0.y, b0.z, b0.w, b1v4.x, b1v4.y, b1v4.z, b1v4.w};
#pragma unroll
            for (int i = 0; i < 8; i++)
#pragma unroll
                for (int j = 0; j < 8; j++)
                    acc[i][j] += av[i] * bv[j];
        }

        if (have_next) {
            const int q = p ^ 1;
            nA.x = isnan(nA.x) ? 0.0f : nA.x;
            nA.y = isnan(nA.y) ? 0.0f : nA.y;
            nA.z = isnan(nA.z) ? 0.0f : nA.z;
            nA.w = isnan(nA.w) ? 0.0f : nA.w;
            As[q][ca + 0][ra] = nA.x;
            As[q][ca + 1][ra] = nA.y;
            As[q][ca + 2][ra] = nA.z;
            As[q][ca + 3][ra] = nA.w;
            *reinterpret_cast<float4*>(&Bs[q][kb][cb]) = nB;
        }

        __syncthreads();
    }

    // --- fused epilogue: +b1, relu, dot with w2, reduce over n, atomic into out ---
    const int hbase = h0 + tx * 8;
    float4 b1a = *reinterpret_cast<const float4*>(b1 + (size_t)b * H_DIM + hbase);
    float4 b1b = *reinterpret_cast<const float4*>(b1 + (size_t)b * H_DIM + hbase + 4);
    float4 w2a = *reinterpret_cast<const float4*>(w2 + (size_t)b * H_DIM + hbase);
    float4 w2b = *reinterpret_cast<const float4*>(w2 + (size_t)b * H_DIM + hbase + 4);
    float b1r[8] = {b1a.x, b1a.y, b1a.z, b1a.w, b1b.x, b1b.y, b1b.z, b1b.w};
    float w2r[8] = {w2a.x, w2a.y, w2a.z, w2a.w, w2b.x, w2b.y, w2b.z, w2b.w};

    float partial[8];
#pragma unroll
    for (int i = 0; i < 8; i++) {
        float s = 0.0f;
#pragma unroll
        for (int j = 0; j < 8; j++) {
            float hv = fmaxf(acc[i][j] + b1r[j], 0.0f);
            s += hv * w2r[j];
        }
        partial[i] = s;
    }

    // Reduce across the 16 tx lanes (contiguous 16-lane groups within each warp).
#pragma unroll
    for (int off = 8; off > 0; off >>= 1) {
#pragma unroll
        for (int i = 0; i < 8; i++)
            partial[i] += __shfl_down_sync(0xffffffffu, partial[i], off, 16);
    }

    if (tx == 0) {
#pragma unroll
        for (int i = 0; i < 8; i++) {
            int t = t0 + ty * 8 + i;
            atomicAdd(&out[(size_t)t * B_DIM + b], partial[i]);
        }
    }
}

extern "C" void kernel_launch(void* const* d_in, const int* in_sizes, int n_in,
                              void* d_out, int out_size) {
    const float* x  = (const float*)d_in[0];
    const float* w1 = (const float*)d_in[1];
    const float* b1 = (const float*)d_in[2];
    const float* w2 = (const float*)d_in[3];
    const float* b2 = (const float*)d_in[4];
    float* out = (float*)d_out;

    (void)in_sizes; (void)n_in; (void)out_size;

    // 1) pre-fill out with b2[b] (out is poisoned before timing)
    {
        int n = T_DIM * B_DIM;
        init_out_kernel<<<(n + 255) / 256, 256>>>(b2, out);
    }

    // 2) fused GEMM + relu + dot
    {
        dim3 grid(T_DIM / BM, H_DIM / BN, B_DIM);  // 32 x 8 x 8
        fused_mlp_kernel<<<grid, NTHREADS>>>(x, w1, b1, w2, out);
    }
}

// round 11
// speedup vs baseline: 2.1029x; 2.1029x over previous
#include <cuda_runtime.h>
#include <cuda_bf16.h>
#include <cstdint>
#include <math.h>

// x_test:[T,B,F] f32, w1:[B,F,H] f32, b1:[B,H], w2:[B,H,1], b2:[B,1], out:[T,B,1]
#define T_DIM 4096
#define B_DIM 8
#define F_DIM 512
#define H_DIM 1024

#define BM 128
#define BN 128
#define BK 32
#define KITERS (F_DIM / BK)   // 16
#define THREADS 512

// ---- static device scratch ----
__device__ __nv_bfloat16 g_x_hi[(size_t)T_DIM * B_DIM * F_DIM];
__device__ __nv_bfloat16 g_x_lo[(size_t)T_DIM * B_DIM * F_DIM];
__device__ __nv_bfloat16 g_w1t_hi[(size_t)B_DIM * H_DIM * F_DIM];  // [b][h][f]
__device__ __nv_bfloat16 g_w1t_lo[(size_t)B_DIM * H_DIM * F_DIM];

// ---- smem layout (bytes) ----
// Tile = BM x BK bf16 = 8192 B. Stage = {Ah, Al, Bh, Bl} = 32768 B. 2 stages.
#define TILE_BYTES  (BM * BK * 2)
#define OFF_AH 0
#define OFF_AL (TILE_BYTES)
#define OFF_BH (2 * TILE_BYTES)
#define OFF_BL (3 * TILE_BYTES)
#define STAGE_BYTES (4 * TILE_BYTES)        // 32768
#define SM_AUX  (2 * STAGE_BYTES)           // 65536
#define OFF_B1  (SM_AUX)                    // 128 f32
#define OFF_W2  (SM_AUX + 512)
#define OFF_RED (SM_AUX + 1024)             // 128 x 4 f32
#define SMEM_TOTAL (SM_AUX + 1024 + 2048)   // 68608

// Row = 32 bf16 = 64B = 4x16B units. Swizzle: unit c ^= (row&7)>>1.
// Gives 8 distinct 16B banks for 8 consecutive rows at fixed c (ldmatrix-safe).
__device__ __forceinline__ uint32_t swz(int row, int c) {
    return (uint32_t)(row * 64 + ((c ^ ((row & 7) >> 1)) << 4));
}

__device__ __forceinline__ uint32_t smem_u32(const void* p) {
    uint32_t a;
    asm("{ .reg .u64 t; cvta.to.shared.u64 t, %1; cvt.u32.u64 %0, t; }"
        : "=r"(a) : "l"(p));
    return a;
}
__device__ __forceinline__ void ldmx4(uint32_t* r, uint32_t addr) {
    asm volatile("ldmatrix.sync.aligned.m8n8.x4.shared.b16 {%0,%1,%2,%3}, [%4];"
                 : "=r"(r[0]), "=r"(r[1]), "=r"(r[2]), "=r"(r[3]) : "r"(addr));
}
__device__ __forceinline__ void mma_bf16(float* c, const uint32_t* a,
                                         uint32_t b0, uint32_t b1) {
    asm volatile(
        "mma.sync.aligned.m16n8k16.row.col.f32.bf16.bf16.f32 "
        "{%0,%1,%2,%3}, {%4,%5,%6,%7}, {%8,%9}, {%0,%1,%2,%3};"
        : "+f"(c[0]), "+f"(c[1]), "+f"(c[2]), "+f"(c[3])
        : "r"(a[0]), "r"(a[1]), "r"(a[2]), "r"(a[3]), "r"(b0), "r"(b1));
}

// ---- prepass 1: x f32 -> (hi, lo) bf16, with nan_to_num ----
__global__ void convert_x_kernel(const float* __restrict__ x) {
    size_t i4 = (size_t)blockIdx.x * blockDim.x + threadIdx.x;
    float4 v = reinterpret_cast<const float4*>(x)[i4];
    v.x = isnan(v.x) ? 0.0f : v.x;
    v.y = isnan(v.y) ? 0.0f : v.y;
    v.z = isnan(v.z) ? 0.0f : v.z;
    v.w = isnan(v.w) ? 0.0f : v.w;
    float f[4] = {v.x, v.y, v.z, v.w};
    __nv_bfloat16 hi[4], lo[4];
#pragma unroll
    for (int j = 0; j < 4; j++) {
        hi[j] = __float2bfloat16(f[j]);
        lo[j] = __float2bfloat16(f[j] - __bfloat162float(hi[j]));
    }
    uint2 ph, pl;
    ph.x = ((uint32_t)*(uint16_t*)&hi[0]) | ((uint32_t)*(uint16_t*)&hi[1] << 16);
    ph.y = ((uint32_t)*(uint16_t*)&hi[2]) | ((uint32_t)*(uint16_t*)&hi[3] << 16);
    pl.x = ((uint32_t)*(uint16_t*)&lo[0]) | ((uint32_t)*(uint16_t*)&lo[1] << 16);
    pl.y = ((uint32_t)*(uint16_t*)&lo[2]) | ((uint32_t)*(uint16_t*)&lo[3] << 16);
    reinterpret_cast<uint2*>(g_x_hi)[i4] = ph;
    reinterpret_cast<uint2*>(g_x_lo)[i4] = pl;
}

// ---- prepass 2: w1 [b][f][h] f32 -> (hi, lo) bf16 transposed [b][h][f] ----
__global__ void convert_w1_kernel(const float* __restrict__ w1) {
    __shared__ float sm[32][33];
    const int b  = blockIdx.z;
    const int h0 = blockIdx.x * 32;
    const int f0 = blockIdx.y * 32;
    const int tx = threadIdx.x;
    const int ty = threadIdx.y;
#pragma unroll
    for (int i = 0; i < 4; i++) {
        int f = f0 + ty + 8 * i;
        sm[ty + 8 * i][tx] = w1[((size_t)b * F_DIM + f) * H_DIM + h0 + tx];
    }
    __syncthreads();
#pragma unroll
    for (int i = 0; i < 4; i++) {
        int h = h0 + ty + 8 * i;
        float v = sm[tx][ty + 8 * i];
        __nv_bfloat16 hi = __float2bfloat16(v);
        __nv_bfloat16 lo = __float2bfloat16(v - __bfloat162float(hi));
        size_t o = ((size_t)b * H_DIM + h) * F_DIM + f0 + tx;
        g_w1t_hi[o] = hi;
        g_w1t_lo[o] = lo;
    }
}

__global__ void init_out_kernel(const float* __restrict__ b2, float* __restrict__ out) {
    int i = blockIdx.x * blockDim.x + threadIdx.x;
    if (i < T_DIM * B_DIM) out[i] = b2[i % B_DIM];
}

// ---- main: mma.sync bf16 GEMM, 3-term split, fused relu-dot epilogue ----
// Grid (T/128, H/128, B) = (32, 8, 8). 512 threads = 16 warps (4x4), warp tile 32x32.
__global__ __launch_bounds__(THREADS, 1)
void gemm_kernel(const float* __restrict__ b1,
                 const float* __restrict__ w2,
                 float* __restrict__ out) {
    extern __shared__ char smem[];
    const uint32_t sbase = smem_u32(smem);
    const int tid  = threadIdx.x;
    const int lane = tid & 31;
    const int wid  = tid >> 5;
    const int wm   = wid >> 2;   // 0..3 (m)
    const int wn   = wid & 3;    // 0..3 (n)
    const int b  = blockIdx.z;
    const int t0 = blockIdx.x * BM;
    const int h0 = blockIdx.y * BN;

    // stage b1/w2 tiles
    if (tid < BN) {
        ((float*)(smem + OFF_B1))[tid] = b1[(size_t)b * H_DIM + h0 + tid];
        ((float*)(smem + OFF_W2))[tid] = w2[(size_t)b * H_DIM + h0 + tid];
    }

    // global load mapping: one 16B unit per thread per tile: row=tid>>2, c=tid&3
    const int grow = tid >> 2;
    const int gc   = tid & 3;
    const __nv_bfloat16* pAh = g_x_hi   + ((size_t)(t0 + grow) * B_DIM + b) * F_DIM + gc * 8;
    const __nv_bfloat16* pAl = g_x_lo   + ((size_t)(t0 + grow) * B_DIM + b) * F_DIM + gc * 8;
    const __nv_bfloat16* pBh = g_w1t_hi + ((size_t)b * H_DIM + h0 + grow) * F_DIM + gc * 8;
    const __nv_bfloat16* pBl = g_w1t_lo + ((size_t)b * H_DIM + h0 + grow) * F_DIM + gc * 8;
    const uint32_t sts_off = swz(grow, gc);

    float acc[2][4][4];
#pragma unroll
    for (int i = 0; i < 2; i++)
#pragma unroll
        for (int j = 0; j < 4; j++)
#pragma unroll
            for (int r = 0; r < 4; r++) acc[i][j][r] = 0.0f;

    // prologue: stage iter 0 into buffer 0
    {
        uint4 a0 = *(const uint4*)pAh;
        uint4 a1 = *(const uint4*)pAl;
        uint4 b0 = *(const uint4*)pBh;
        uint4 b1r = *(const uint4*)pBl;
        *(uint4*)(smem + OFF_AH + sts_off) = a0;
        *(uint4*)(smem + OFF_AL + sts_off) = a1;
        *(uint4*)(smem + OFF_BH + sts_off) = b0;
        *(uint4*)(smem + OFF_BL + sts_off) = b1r;
    }
    __syncthreads();

    // ldmatrix lane address components (invariant per thread)
    const int a_row = wm * 32 + (lane & 15);           // + i*16
    const int a_chi = (lane >> 4) & 1;                 // k-half select
    const int b_row = wn * 32 + ((lane & 16) ? 8 : 0) + (lane & 7);  // + pair*16
    const int b_chi = (lane & 8) ? 1 : 0;

    for (int it = 0; it < KITERS; it++) {
        const int p = it & 1;
        uint4 nAh, nAl, nBh, nBl;
        const bool more = (it + 1 < KITERS);
        if (more) {
            const size_t go = (size_t)(it + 1) * BK;
            nAh = *(const uint4*)(pAh + go);
            nAl = *(const uint4*)(pAl + go);
            nBh = *(const uint4*)(pBh + go);
            nBl = *(const uint4*)(pBl + go);
        }

        const uint32_t sb = sbase + (uint32_t)p * STAGE_BYTES;
#pragma unroll
        for (int ks = 0; ks < 2; ks++) {
            uint32_t ah[2][4], al[2][4], bh[2][4], bl[2][4];
#pragma unroll
            for (int i = 0; i < 2; i++) {
                int r = a_row + i * 16;
                ldmx4(ah[i], sb + OFF_AH + swz(r, ks * 2 + a_chi));
            }
#pragma unroll
            for (int q = 0; q < 2; q++) {
                int r = b_row + q * 16;
                ldmx4(bh[q], sb + OFF_BH + swz(r, ks * 2 + b_chi));
            }
            // hi * hi
#pragma unroll
            for (int i = 0; i < 2; i++)
#pragma unroll
                for (int j = 0; j < 4; j++)
                    mma_bf16(acc[i][j], ah[i], bh[j >> 1][(j & 1) * 2],
                             bh[j >> 1][(j & 1) * 2 + 1]);
            // lo * hi
#pragma unroll
            for (int i = 0; i < 2; i++) {
                int r = a_row + i * 16;
                ldmx4(al[i], sb + OFF_AL + swz(r, ks * 2 + a_chi));
            }
#pragma unroll
            for (int i = 0; i < 2; i++)
#pragma unroll
                for (int j = 0; j < 4; j++)
                    mma_bf16(acc[i][j], al[i], bh[j >> 1][(j & 1) * 2],
                             bh[j >> 1][(j & 1) * 2 + 1]);
            // hi * lo
#pragma unroll
            for (int q = 0; q < 2; q++) {
                int r = b_row + q * 16;
                ldmx4(bl[q], sb + OFF_BL + swz(r, ks * 2 + b_chi));
            }
#pragma unroll
            for (int i = 0; i < 2; i++)
#pragma unroll
                for (int j = 0; j < 4; j++)
                    mma_bf16(acc[i][j], ah[i], bl[j >> 1][(j & 1) * 2],
                             bl[j >> 1][(j & 1) * 2 + 1]);
        }

        if (more) {
            char* sd = smem + (size_t)((it + 1) & 1) * STAGE_BYTES;
            *(uint4*)(sd + OFF_AH + sts_off) = nAh;
            *(uint4*)(sd + OFF_AL + sts_off) = nAl;
            *(uint4*)(sd + OFF_BH + sts_off) = nBh;
            *(uint4*)(sd + OFF_BL + sts_off) = nBl;
        }
        __syncthreads();
    }

    // ---- fused epilogue ----
    const float* b1s = (const float*)(smem + OFF_B1);
    const float* w2s = (const float*)(smem + OFF_W2);
    float* red = (float*)(smem + OFF_RED);

#pragma unroll
    for (int i = 0; i < 2; i++) {
        float slo = 0.0f, shi = 0.0f;
#pragma unroll
        for (int j = 0; j < 4; j++) {
            int h = wn * 32 + j * 8 + (lane & 3) * 2;
            float bb0 = b1s[h], bb1 = b1s[h + 1];
            float ww0 = w2s[h], ww1 = w2s[h + 1];
            slo += fmaxf(acc[i][j][0] + bb0, 0.0f) * ww0
                 + fmaxf(acc[i][j][1] + bb1, 0.0f) * ww1;
            shi += fmaxf(acc[i][j][2] + bb0, 0.0f) * ww0
                 + fmaxf(acc[i][j][3] + bb1, 0.0f) * ww1;
        }
        slo += __shfl_xor_sync(0xffffffffu, slo, 1);
        slo += __shfl_xor_sync(0xffffffffu, slo, 2);
        shi += __shfl_xor_sync(0xffffffffu, shi, 1);
        shi += __shfl_xor_sync(0xffffffffu, shi, 2);
        if ((lane & 3) == 0) {
            int r = wm * 32 + i * 16 + (lane >> 2);
            red[r * 4 + wn] = slo;
            red[(r + 8) * 4 + wn] = shi;
        }
    }
    __syncthreads();
    if (tid < BM) {
        float s = red[tid * 4] + red[tid * 4 + 1] + red[tid * 4 + 2] + red[tid * 4 + 3];
        atomicAdd(&out[(size_t)(t0 + tid) * B_DIM + b], s);
    }
}

extern "C" void kernel_launch(void* const* d_in, const int* in_sizes, int n_in,
                              void* d_out, int out_size) {
    const float* x  = (const float*)d_in[0];
    const float* w1 = (const float*)d_in[1];
    const float* b1 = (const float*)d_in[2];
    const float* w2 = (const float*)d_in[3];
    const float* b2 = (const float*)d_in[4];
    float* out = (float*)d_out;
    (void)in_sizes; (void)n_in; (void)out_size;

    cudaFuncSetAttribute(gemm_kernel, cudaFuncAttributeMaxDynamicSharedMemorySize,
                         SMEM_TOTAL);

    {
        size_t n4 = (size_t)T_DIM * B_DIM * F_DIM / 4;
        convert_x_kernel<<<(unsigned)(n4 / 256), 256>>>(x);
        dim3 g(H_DIM / 32, F_DIM / 32, B_DIM);
        convert_w1_kernel<<<g, dim3(32, 8)>>>(w1);
    }
    {
        int n = T_DIM * B_DIM;
        init_out_kernel<<<(n + 255) / 256, 256>>>(b2, out);
    }
    {
        dim3 grid(T_DIM / BM, H_DIM / BN, B_DIM);   // 32 x 8 x 8
        gemm_kernel<<<grid, THREADS, SMEM_TOTAL>>>(b1, w2, out);
    }
}